// round 7
// baseline (speedup 1.0000x reference)
#include <cuda_runtime.h>
#include <cstdint>
#include <stddef.h>

// Problem constants (match reference_code)
#define NN      16384
#define IN_DIM  64
#define L0      32
#define L1      48
#define L2      64
#define MLP_H   32
#define NCLS    2
#define CAPN    128   // max neighbors per row (Poisson(~33): P(deg>=128) ~ 1e-30)

// ---------------- scratch (__device__ globals; no allocation allowed) ----------
__device__ int   d_nbr[(size_t)NN * CAPN];   // 8 MB  ELL neighbor indices
__device__ int   d_cnt[NN];
__device__ float d_dinv[NN];
__device__ float d_bufA[(size_t)NN * 64];    // 4 MB  ping
__device__ float d_bufB[(size_t)NN * 64];    // 4 MB  pong
__device__ float d_part[128 * 64];           // column partial sums

// ---------------------------------------------------------------------------
// Kernel 1: stream 1 GiB dense adjacency once; build ELL lists + degrees.
// One warp per row. HBM-bound. __ldcs streams (keeps L2 for gather tables).
// Deterministic: fixed traversal + warp exclusive scan (no atomics).
// ---------------------------------------------------------------------------
__global__ __launch_bounds__(256) void build_sparse(const float* __restrict__ adj) {
    const int warp = blockIdx.x * 8 + (threadIdx.x >> 5);
    const int lane = threadIdx.x & 31;
    const int row  = warp;  // 2048 blocks x 8 warps -> 16384 rows

    const uint4* __restrict__ arow =
        reinterpret_cast<const uint4*>(adj + (size_t)row * NN);

    int loc[32];
    int lc = 0;      // stored candidates (capped at 32)
    int cnt = 0;     // true nonzero count (uncapped)

    #pragma unroll 1
    for (int it = 0; it < 16; it++) {
        const int base = it * 256;
        uint4 v[8];
        #pragma unroll
        for (int u = 0; u < 8; u++)
            v[u] = __ldcs(&arow[base + u * 32 + lane]);
        unsigned o = 0u;
        #pragma unroll
        for (int u = 0; u < 8; u++)
            o |= (v[u].x | v[u].y | v[u].z | v[u].w);
        if (o) {
            #pragma unroll
            for (int u = 0; u < 8; u++) {
                const int c = 4 * (base + u * 32 + lane);
                if (v[u].x) { if (lc < 32) loc[lc++] = c;     cnt++; }
                if (v[u].y) { if (lc < 32) loc[lc++] = c + 1; cnt++; }
                if (v[u].z) { if (lc < 32) loc[lc++] = c + 2; cnt++; }
                if (v[u].w) { if (lc < 32) loc[lc++] = c + 3; cnt++; }
            }
        }
    }
    const int stored = lc;

    const unsigned m = 0xffffffffu;
    int incl = stored;
    #pragma unroll
    for (int d = 1; d < 32; d <<= 1) {
        int nv = __shfl_up_sync(m, incl, d);
        if (lane >= d) incl += nv;
    }
    const int excl = incl - stored;

    int deg = cnt;
    #pragma unroll
    for (int d = 16; d > 0; d >>= 1) deg += __shfl_xor_sync(m, deg, d);

    int* __restrict__ nl = d_nbr + (size_t)row * CAPN;
    for (int t = 0; t < stored; t++) {
        const int p = excl + t;
        if (p < CAPN) nl[p] = loc[t];
    }
    if (lane == 31) {
        const int tot = incl;
        d_cnt[row] = tot < CAPN ? tot : CAPN;
    }
    if (lane == 0)
        d_dinv[row] = rsqrtf((float)deg + 1.0f);   // deg includes self loop
}

// ---------------------------------------------------------------------------
// Kernel 2 (x3): out = epilogue( H @ W ), H tile in shared, W col in registers.
// MODE 0: out = dinv[row] * acc
// MODE 1: out = dinv[row] * relu(acc + bias[tx])
// MODE 2: out = relu(acc + bias[tx])
// MODE 3: out = acc                     (raw; NO dependency on dinv)
// ---------------------------------------------------------------------------
template <int KI, int KO, int TPB, int MODE>
__global__ __launch_bounds__(TPB) void gemm_scale(const float* __restrict__ H,
                                                  const float* __restrict__ W,
                                                  const float* __restrict__ dinv,
                                                  const float* __restrict__ bias,
                                                  float* __restrict__ out,
                                                  int row_base) {
    constexpr int ROWS = 32;
    constexpr int NR   = TPB / KO;          // rows per sweep
    constexpr int RPT  = ROWS / NR;         // rows per thread (=4)
    __shared__ float Hs[ROWS * KI];

    const int tid  = threadIdx.x;
    const int row0 = row_base + blockIdx.x * ROWS;

    const float4* __restrict__ Hg =
        reinterpret_cast<const float4*>(H + (size_t)row0 * KI);
    #pragma unroll
    for (int i = tid; i < ROWS * KI / 4; i += TPB)
        reinterpret_cast<float4*>(Hs)[i] = Hg[i];

    const int tx = tid % KO;
    const int ty = tid / KO;
    float wreg[KI];
    #pragma unroll
    for (int k = 0; k < KI; k++) wreg[k] = __ldg(&W[k * KO + tx]);
    __syncthreads();

    float acc[RPT];
    #pragma unroll
    for (int i = 0; i < RPT; i++) acc[i] = 0.f;

    #pragma unroll
    for (int k4 = 0; k4 < KI / 4; k4++) {
        #pragma unroll
        for (int i = 0; i < RPT; i++) {
            const float4 h =
                *reinterpret_cast<const float4*>(&Hs[(ty + i * NR) * KI + 4 * k4]);
            acc[i] += h.x * wreg[4 * k4 + 0] + h.y * wreg[4 * k4 + 1]
                    + h.z * wreg[4 * k4 + 2] + h.w * wreg[4 * k4 + 3];
        }
    }

    #pragma unroll
    for (int i = 0; i < RPT; i++) {
        const int row = row0 + ty + i * NR;
        float v;
        if (MODE == 0)      v = dinv[row] * acc[i];
        else if (MODE == 1) v = dinv[row] * fmaxf(acc[i] + bias[tx], 0.f);
        else if (MODE == 2) v = fmaxf(acc[i] + bias[tx], 0.f);
        else                v = acc[i];
        out[(size_t)row * KO + tx] = v;
    }
}

// ---------------------------------------------------------------------------
// Kernel 3 (x3): gather-aggregate over neighbor lists (L2-resident table).
// 8-deep unroll, two int4 index fetches, 4 independent accumulators per half
// -> 8 outstanding gathers/warp (hides ~240cyc L2 latency).
// MODE 0 (layer 1, X = raw nf@W0): weights gathers by dinv[j] (uniform load),
//        self by dinv[i];  out = dinv_i * relu(dinv_i*sum + b)
// MODE 1 (X = S = dinv.h):  out = dinv_i * sum
// ---------------------------------------------------------------------------
template <int KO, int MODE>
__global__ __launch_bounds__(256) void spmm_agg(const float* __restrict__ X,
                                                const float* __restrict__ bias,
                                                float* __restrict__ out) {
    const int warp = blockIdx.x * 8 + (threadIdx.x >> 5);
    const int lane = threadIdx.x & 31;
    const int row  = warp;

    const float di = d_dinv[row];
    const float selfw = (MODE == 0) ? di : 1.0f;

    const float* __restrict__ self = X + (size_t)row * KO;
    float a0 = selfw * self[lane], b0 = 0.f, c0 = 0.f, e0 = 0.f;
    float a1 = 0.f, b1 = 0.f, c1 = 0.f, e1 = 0.f;
    const bool has1 = (KO > 32) && (lane + 32 < KO);
    if (has1) a1 = selfw * self[32 + lane];

    const int n = d_cnt[row];
    const int* __restrict__ nl = d_nbr + (size_t)row * CAPN;

    int k = 0;
    for (; k + 8 <= n; k += 8) {
        const int4 ja = *reinterpret_cast<const int4*>(nl + k);      // uniform bcast
        const int4 jb = *reinterpret_cast<const int4*>(nl + k + 4);
        const float* __restrict__ p0 = X + (size_t)ja.x * KO;
        const float* __restrict__ p1 = X + (size_t)ja.y * KO;
        const float* __restrict__ p2 = X + (size_t)ja.z * KO;
        const float* __restrict__ p3 = X + (size_t)ja.w * KO;
        const float* __restrict__ p4 = X + (size_t)jb.x * KO;
        const float* __restrict__ p5 = X + (size_t)jb.y * KO;
        const float* __restrict__ p6 = X + (size_t)jb.z * KO;
        const float* __restrict__ p7 = X + (size_t)jb.w * KO;
        float d0 = 1.f, d1 = 1.f, d2 = 1.f, d3 = 1.f,
              d4 = 1.f, d5 = 1.f, d6 = 1.f, d7 = 1.f;
        if (MODE == 0) {
            d0 = __ldg(&d_dinv[ja.x]); d1 = __ldg(&d_dinv[ja.y]);
            d2 = __ldg(&d_dinv[ja.z]); d3 = __ldg(&d_dinv[ja.w]);
            d4 = __ldg(&d_dinv[jb.x]); d5 = __ldg(&d_dinv[jb.y]);
            d6 = __ldg(&d_dinv[jb.z]); d7 = __ldg(&d_dinv[jb.w]);
        }
        const float x0 = __ldg(&p0[lane]);
        const float x1 = __ldg(&p1[lane]);
        const float x2 = __ldg(&p2[lane]);
        const float x3 = __ldg(&p3[lane]);
        const float x4 = __ldg(&p4[lane]);
        const float x5 = __ldg(&p5[lane]);
        const float x6 = __ldg(&p6[lane]);
        const float x7 = __ldg(&p7[lane]);
        if (MODE == 0) {
            a0 = fmaf(d0, x0, a0); b0 = fmaf(d1, x1, b0);
            c0 = fmaf(d2, x2, c0); e0 = fmaf(d3, x3, e0);
            a0 = fmaf(d4, x4, a0); b0 = fmaf(d5, x5, b0);
            c0 = fmaf(d6, x6, c0); e0 = fmaf(d7, x7, e0);
        } else {
            a0 += x0; b0 += x1; c0 += x2; e0 += x3;
            a0 += x4; b0 += x5; c0 += x6; e0 += x7;
        }
        if (has1) {
            const float y0 = __ldg(&p0[32 + lane]);
            const float y1 = __ldg(&p1[32 + lane]);
            const float y2 = __ldg(&p2[32 + lane]);
            const float y3 = __ldg(&p3[32 + lane]);
            const float y4 = __ldg(&p4[32 + lane]);
            const float y5 = __ldg(&p5[32 + lane]);
            const float y6 = __ldg(&p6[32 + lane]);
            const float y7 = __ldg(&p7[32 + lane]);
            if (MODE == 0) {
                a1 = fmaf(d0, y0, a1); b1 = fmaf(d1, y1, b1);
                c1 = fmaf(d2, y2, c1); e1 = fmaf(d3, y3, e1);
                a1 = fmaf(d4, y4, a1); b1 = fmaf(d5, y5, b1);
                c1 = fmaf(d6, y6, c1); e1 = fmaf(d7, y7, e1);
            } else {
                a1 += y0; b1 += y1; c1 += y2; e1 += y3;
                a1 += y4; b1 += y5; c1 += y6; e1 += y7;
            }
        }
    }
    for (; k < n; k++) {
        const int j = nl[k];
        const float* __restrict__ p = X + (size_t)j * KO;
        const float dj = (MODE == 0) ? __ldg(&d_dinv[j]) : 1.0f;
        a0 = fmaf(dj, __ldg(&p[lane]), a0);
        if (has1) a1 = fmaf(dj, __ldg(&p[32 + lane]), a1);
    }

    const float s0 = (a0 + b0) + (c0 + e0);
    if (MODE == 0) {
        out[(size_t)row * KO + lane] = di * fmaxf(di * s0 + bias[lane], 0.f);
        if (has1) {
            const float s1 = (a1 + b1) + (c1 + e1);
            out[(size_t)row * KO + 32 + lane] =
                di * fmaxf(di * s1 + bias[32 + lane], 0.f);
        }
    } else {
        out[(size_t)row * KO + lane] = di * s0;
        if (has1)
            out[(size_t)row * KO + 32 + lane] = di * ((a1 + b1) + (c1 + e1));
    }
}

// ---------------------------------------------------------------------------
// Kernel 4: column partial sums of H3 (16384 x 64) -> 128 partials per column
// ---------------------------------------------------------------------------
__global__ void colsum(const float* __restrict__ H, float* __restrict__ part) {
    __shared__ float sh[4][64];
    const int col = threadIdx.x;   // 64
    const int ty  = threadIdx.y;   // 4
    const int row0 = blockIdx.x * 128;
    float s = 0.f;
    for (int r = ty; r < 128; r += 4)
        s += H[(size_t)(row0 + r) * 64 + col];
    sh[ty][col] = s;
    __syncthreads();
    if (ty == 0)
        part[blockIdx.x * 64 + col] = sh[0][col] + sh[1][col] + sh[2][col] + sh[3][col];
}

// ---------------------------------------------------------------------------
// Kernel 5: finish mean, MLP head (elu), logits, softmax. Single block, 64 thr.
// ---------------------------------------------------------------------------
__global__ void head(const float* __restrict__ part,
                     const float* __restrict__ Wh1, const float* __restrict__ bh1,
                     const float* __restrict__ Wh2, const float* __restrict__ bh2,
                     float* __restrict__ out) {
    __shared__ float g[64], h1[32], lg[2];
    const int t = threadIdx.x;  // 64 threads
    float s = 0.f;
    for (int b = 0; b < 128; b++) s += part[b * 64 + t];
    g[t] = s * (1.0f / (float)NN);
    __syncthreads();
    if (t < MLP_H) {
        float a = bh1[t];
        #pragma unroll
        for (int k = 0; k < 64; k++) a += g[k] * Wh1[k * MLP_H + t];
        h1[t] = (a > 0.f) ? a : expm1f(a);   // elu, alpha=1
    }
    __syncthreads();
    if (t < NCLS) {
        float a = bh2[t];
        #pragma unroll
        for (int k = 0; k < MLP_H; k++) a += h1[k] * Wh2[k * NCLS + t];
        lg[t] = a;
        out[t] = a;                          // logits
    }
    __syncthreads();
    if (t == 0) {
        const float mx = fmaxf(lg[0], lg[1]);
        const float e0 = expf(lg[0] - mx), e1 = expf(lg[1] - mx);
        const float inv = 1.f / (e0 + e1);
        out[2] = e0 * inv;                   // probs
        out[3] = e1 * inv;
    }
}

// ---------------------------------------------------------------------------
extern "C" void kernel_launch(void* const* d_in, const int* in_sizes, int n_in,
                              void* d_out, int out_size) {
    const float* nf   = (const float*)d_in[0];   // [N, 64]
    const float* adj  = (const float*)d_in[1];   // [N, N]
    const float* W0   = (const float*)d_in[2];   // [64, 32]
    const float* b0   = (const float*)d_in[3];
    const float* W1   = (const float*)d_in[4];   // [32, 48]
    const float* b1   = (const float*)d_in[5];
    const float* W2   = (const float*)d_in[6];   // [48, 64]
    const float* b2   = (const float*)d_in[7];
    const float* Wh1  = (const float*)d_in[8];   // [64, 32]
    const float* bh1  = (const float*)d_in[9];
    const float* Wh2  = (const float*)d_in[10];  // [32, 2]
    const float* bh2  = (const float*)d_in[11];
    float* out = (float*)d_out;

    float *bufA, *bufB, *pt, *dinv;
    cudaGetSymbolAddress((void**)&bufA, d_bufA);
    cudaGetSymbolAddress((void**)&bufB, d_bufB);
    cudaGetSymbolAddress((void**)&pt,   d_part);
    cudaGetSymbolAddress((void**)&dinv, d_dinv);

    // gemm1 computes RAW nf@W0 (MODE 3: no dinv dependency) -> legal before
    // build_sparse. Split into 3 chunks so build_sparse lands on the profiled
    // launch slot (index 3).
    gemm_scale<IN_DIM, L0, 256, 3><<<171, 256>>>(nf, W0, nullptr, nullptr, bufA, 0);
    gemm_scale<IN_DIM, L0, 256, 3><<<171, 256>>>(nf, W0, nullptr, nullptr, bufA, 171 * 32);
    gemm_scale<IN_DIM, L0, 256, 3><<<170, 256>>>(nf, W0, nullptr, nullptr, bufA, 342 * 32);

    // 1 GiB streaming pass; HBM-bound  (launch index 3 -> ncu)
    build_sparse<<<NN / 8, 256>>>(adj);

    // layer 1 aggregate: dinv applied per-neighbor inside (MODE 0)
    spmm_agg<L0, 0><<<NN / 8, 256>>>(bufA, b0, bufB);     // bufB = S1 = dinv.h1

    // layer 2 (aggregate-first: gather width 32, then 32->48 GEMM)
    spmm_agg<L0, 1><<<NN / 8, 256>>>(bufB, nullptr, bufA);                     // z2
    gemm_scale<L0, L1, 384, 1><<<NN / 32, 384>>>(bufA, W1, dinv, b1, bufB, 0); // S2

    // layer 3 (aggregate-first: gather width 48, then 48->64 GEMM)
    spmm_agg<L1, 1><<<NN / 8, 256>>>(bufB, nullptr, bufA);                     // z3
    gemm_scale<L1, L2, 512, 2><<<NN / 32, 512>>>(bufA, W2, dinv, b2, bufB, 0); // h3

    // mean-pool + MLP + softmax
    colsum<<<128, dim3(64, 4)>>>(bufB, pt);
    head<<<1, 64>>>(pt, Wh1, bh1, Wh2, bh2, out);
}

// round 8
// speedup vs baseline: 1.0267x; 1.0267x over previous
#include <cuda_runtime.h>
#include <cstdint>
#include <stddef.h>

// Problem constants (match reference_code)
#define NN      16384
#define IN_DIM  64
#define L0      32
#define L1      48
#define L2      64
#define MLP_H   32
#define NCLS    2
#define CAPN    128   // max neighbors per row (Poisson(~33): P(deg>=128) ~ 1e-30)

// ---------------- scratch (__device__ globals; no allocation allowed) ----------
__device__ int   d_nbr[(size_t)NN * CAPN];   // 8 MB  ELL neighbor indices
__device__ int   d_cnt[NN];
__device__ float d_dinv[NN];
__device__ float d_bufA[(size_t)NN * 64];    // 4 MB  ping
__device__ float d_bufB[(size_t)NN * 64];    // 4 MB  pong
__device__ float d_part[128 * 64];           // column partial sums

// ---------------------------------------------------------------------------
// Kernel 1 v2: stream 1 GiB dense adjacency once; build ELL lists + degrees.
// One warp per row. Double-buffered prefetch: next 4KB block always in flight
// while the current one is OR-scanned -> smooth, deep LDG stream (~16
// outstanding LDG.128/warp) instead of bursty load-then-drain.
// Deterministic: fixed traversal + warp exclusive scan (no atomics).
// ---------------------------------------------------------------------------
__global__ __launch_bounds__(256) void build_sparse(const float* __restrict__ adj) {
    const int warp = blockIdx.x * 8 + (threadIdx.x >> 5);
    const int lane = threadIdx.x & 31;
    const int row  = warp;  // 2048 blocks x 8 warps -> 16384 rows

    const uint4* __restrict__ arow =
        reinterpret_cast<const uint4*>(adj + (size_t)row * NN);

    int loc[16];
    int lc = 0;      // stored candidates (capped at 16 per lane)
    int cnt = 0;     // true nonzero count (uncapped)

    uint4 va[8], vb[8];

    #define LOADB(buf, it_) do {                                         \
        const int _b = (it_) * 256;                                      \
        _Pragma("unroll")                                                \
        for (int _u = 0; _u < 8; _u++)                                   \
            buf[_u] = __ldcs(&arow[_b + _u * 32 + lane]);                \
    } while (0)

    #define PROCB(buf, it_) do {                                         \
        const int _b = (it_) * 256;                                      \
        unsigned _o = 0u;                                                \
        _Pragma("unroll")                                                \
        for (int _u = 0; _u < 8; _u++)                                   \
            _o |= (buf[_u].x | buf[_u].y | buf[_u].z | buf[_u].w);       \
        if (_o) {                                                        \
            _Pragma("unroll")                                            \
            for (int _u = 0; _u < 8; _u++) {                             \
                const int _c = 4 * (_b + _u * 32 + lane);                \
                if (buf[_u].x) { if (lc < 16) loc[lc] = _c;     lc++; cnt++; } \
                if (buf[_u].y) { if (lc < 16) loc[lc] = _c + 1; lc++; cnt++; } \
                if (buf[_u].z) { if (lc < 16) loc[lc] = _c + 2; lc++; cnt++; } \
                if (buf[_u].w) { if (lc < 16) loc[lc] = _c + 3; lc++; cnt++; } \
            }                                                            \
        }                                                                \
    } while (0)

    LOADB(va, 0);
    #pragma unroll 1
    for (int it2 = 0; it2 < 8; it2++) {
        LOADB(vb, 2 * it2 + 1);          // prefetch odd block
        PROCB(va, 2 * it2);              // process even block
        if (it2 < 7) LOADB(va, 2 * it2 + 2);  // prefetch next even block
        PROCB(vb, 2 * it2 + 1);          // process odd block
    }
    #undef LOADB
    #undef PROCB

    const int stored = lc < 16 ? lc : 16;

    // warp-wide exclusive scan of per-lane stored counts (deterministic order)
    const unsigned m = 0xffffffffu;
    int incl = stored;
    #pragma unroll
    for (int d = 1; d < 32; d <<= 1) {
        int nv = __shfl_up_sync(m, incl, d);
        if (lane >= d) incl += nv;
    }
    const int excl = incl - stored;

    int deg = cnt;
    #pragma unroll
    for (int d = 16; d > 0; d >>= 1) deg += __shfl_xor_sync(m, deg, d);

    int* __restrict__ nl = d_nbr + (size_t)row * CAPN;
    for (int t = 0; t < stored; t++) {
        const int p = excl + t;
        if (p < CAPN) nl[p] = loc[t];
    }
    if (lane == 31) {
        const int tot = incl;
        d_cnt[row] = tot < CAPN ? tot : CAPN;
    }
    if (lane == 0)
        d_dinv[row] = rsqrtf((float)deg + 1.0f);   // deg includes self loop
}

// ---------------------------------------------------------------------------
// Kernel 2 (x3): out = epilogue( H @ W ), H tile in shared, W col in registers.
// MODE 0: out = dinv[row] * acc
// MODE 1: out = dinv[row] * relu(acc + bias[tx])
// MODE 2: out = relu(acc + bias[tx])
// MODE 3: out = acc                     (raw; NO dependency on dinv)
// ---------------------------------------------------------------------------
template <int KI, int KO, int TPB, int MODE>
__global__ __launch_bounds__(TPB) void gemm_scale(const float* __restrict__ H,
                                                  const float* __restrict__ W,
                                                  const float* __restrict__ dinv,
                                                  const float* __restrict__ bias,
                                                  float* __restrict__ out) {
    constexpr int ROWS = 32;
    constexpr int NR   = TPB / KO;          // rows per sweep
    constexpr int RPT  = ROWS / NR;         // rows per thread (=4)
    __shared__ float Hs[ROWS * KI];

    const int tid  = threadIdx.x;
    const int row0 = blockIdx.x * ROWS;

    const float4* __restrict__ Hg =
        reinterpret_cast<const float4*>(H + (size_t)row0 * KI);
    #pragma unroll
    for (int i = tid; i < ROWS * KI / 4; i += TPB)
        reinterpret_cast<float4*>(Hs)[i] = Hg[i];

    const int tx = tid % KO;
    const int ty = tid / KO;
    float wreg[KI];
    #pragma unroll
    for (int k = 0; k < KI; k++) wreg[k] = __ldg(&W[k * KO + tx]);
    __syncthreads();

    float acc[RPT];
    #pragma unroll
    for (int i = 0; i < RPT; i++) acc[i] = 0.f;

    #pragma unroll
    for (int k4 = 0; k4 < KI / 4; k4++) {
        #pragma unroll
        for (int i = 0; i < RPT; i++) {
            const float4 h =
                *reinterpret_cast<const float4*>(&Hs[(ty + i * NR) * KI + 4 * k4]);
            acc[i] += h.x * wreg[4 * k4 + 0] + h.y * wreg[4 * k4 + 1]
                    + h.z * wreg[4 * k4 + 2] + h.w * wreg[4 * k4 + 3];
        }
    }

    #pragma unroll
    for (int i = 0; i < RPT; i++) {
        const int row = row0 + ty + i * NR;
        float v;
        if (MODE == 0)      v = dinv[row] * acc[i];
        else if (MODE == 1) v = dinv[row] * fmaxf(acc[i] + bias[tx], 0.f);
        else if (MODE == 2) v = fmaxf(acc[i] + bias[tx], 0.f);
        else                v = acc[i];
        out[(size_t)row * KO + tx] = v;
    }
}

// ---------------------------------------------------------------------------
// Kernel 3 (x3): gather-aggregate over neighbor lists (L2-resident table).
// 8-deep unroll, two int4 index fetches, 4 independent accumulators per half
// -> 8 outstanding gathers/warp.
// MODE 0 (layer 1, X = raw nf@W0): weights gathers by dinv[j] (uniform load),
//        self by dinv[i];  out = dinv_i * relu(dinv_i*sum + b)
// MODE 1 (X = S = dinv.h):  out = dinv_i * sum
// ---------------------------------------------------------------------------
template <int KO, int MODE>
__global__ __launch_bounds__(256) void spmm_agg(const float* __restrict__ X,
                                                const float* __restrict__ bias,
                                                float* __restrict__ out) {
    const int warp = blockIdx.x * 8 + (threadIdx.x >> 5);
    const int lane = threadIdx.x & 31;
    const int row  = warp;

    const float di = d_dinv[row];
    const float selfw = (MODE == 0) ? di : 1.0f;

    const float* __restrict__ self = X + (size_t)row * KO;
    float a0 = selfw * self[lane], b0 = 0.f, c0 = 0.f, e0 = 0.f;
    float a1 = 0.f, b1 = 0.f, c1 = 0.f, e1 = 0.f;
    const bool has1 = (KO > 32) && (lane + 32 < KO);
    if (has1) a1 = selfw * self[32 + lane];

    const int n = d_cnt[row];
    const int* __restrict__ nl = d_nbr + (size_t)row * CAPN;

    int k = 0;
    for (; k + 8 <= n; k += 8) {
        const int4 ja = *reinterpret_cast<const int4*>(nl + k);      // uniform bcast
        const int4 jb = *reinterpret_cast<const int4*>(nl + k + 4);
        const float* __restrict__ p0 = X + (size_t)ja.x * KO;
        const float* __restrict__ p1 = X + (size_t)ja.y * KO;
        const float* __restrict__ p2 = X + (size_t)ja.z * KO;
        const float* __restrict__ p3 = X + (size_t)ja.w * KO;
        const float* __restrict__ p4 = X + (size_t)jb.x * KO;
        const float* __restrict__ p5 = X + (size_t)jb.y * KO;
        const float* __restrict__ p6 = X + (size_t)jb.z * KO;
        const float* __restrict__ p7 = X + (size_t)jb.w * KO;
        float d0 = 1.f, d1 = 1.f, d2 = 1.f, d3 = 1.f,
              d4 = 1.f, d5 = 1.f, d6 = 1.f, d7 = 1.f;
        if (MODE == 0) {
            d0 = __ldg(&d_dinv[ja.x]); d1 = __ldg(&d_dinv[ja.y]);
            d2 = __ldg(&d_dinv[ja.z]); d3 = __ldg(&d_dinv[ja.w]);
            d4 = __ldg(&d_dinv[jb.x]); d5 = __ldg(&d_dinv[jb.y]);
            d6 = __ldg(&d_dinv[jb.z]); d7 = __ldg(&d_dinv[jb.w]);
        }
        const float x0 = __ldg(&p0[lane]);
        const float x1 = __ldg(&p1[lane]);
        const float x2 = __ldg(&p2[lane]);
        const float x3 = __ldg(&p3[lane]);
        const float x4 = __ldg(&p4[lane]);
        const float x5 = __ldg(&p5[lane]);
        const float x6 = __ldg(&p6[lane]);
        const float x7 = __ldg(&p7[lane]);
        if (MODE == 0) {
            a0 = fmaf(d0, x0, a0); b0 = fmaf(d1, x1, b0);
            c0 = fmaf(d2, x2, c0); e0 = fmaf(d3, x3, e0);
            a0 = fmaf(d4, x4, a0); b0 = fmaf(d5, x5, b0);
            c0 = fmaf(d6, x6, c0); e0 = fmaf(d7, x7, e0);
        } else {
            a0 += x0; b0 += x1; c0 += x2; e0 += x3;
            a0 += x4; b0 += x5; c0 += x6; e0 += x7;
        }
        if (has1) {
            const float y0 = __ldg(&p0[32 + lane]);
            const float y1 = __ldg(&p1[32 + lane]);
            const float y2 = __ldg(&p2[32 + lane]);
            const float y3 = __ldg(&p3[32 + lane]);
            const float y4 = __ldg(&p4[32 + lane]);
            const float y5 = __ldg(&p5[32 + lane]);
            const float y6 = __ldg(&p6[32 + lane]);
            const float y7 = __ldg(&p7[32 + lane]);
            if (MODE == 0) {
                a1 = fmaf(d0, y0, a1); b1 = fmaf(d1, y1, b1);
                c1 = fmaf(d2, y2, c1); e1 = fmaf(d3, y3, e1);
                a1 = fmaf(d4, y4, a1); b1 = fmaf(d5, y5, b1);
                c1 = fmaf(d6, y6, c1); e1 = fmaf(d7, y7, e1);
            } else {
                a1 += y0; b1 += y1; c1 += y2; e1 += y3;
                a1 += y4; b1 += y5; c1 += y6; e1 += y7;
            }
        }
    }
    for (; k < n; k++) {
        const int j = nl[k];
        const float* __restrict__ p = X + (size_t)j * KO;
        const float dj = (MODE == 0) ? __ldg(&d_dinv[j]) : 1.0f;
        a0 = fmaf(dj, __ldg(&p[lane]), a0);
        if (has1) a1 = fmaf(dj, __ldg(&p[32 + lane]), a1);
    }

    const float s0 = (a0 + b0) + (c0 + e0);
    if (MODE == 0) {
        out[(size_t)row * KO + lane] = di * fmaxf(di * s0 + bias[lane], 0.f);
        if (has1) {
            const float s1 = (a1 + b1) + (c1 + e1);
            out[(size_t)row * KO + 32 + lane] =
                di * fmaxf(di * s1 + bias[32 + lane], 0.f);
        }
    } else {
        out[(size_t)row * KO + lane] = di * s0;
        if (has1)
            out[(size_t)row * KO + 32 + lane] = di * ((a1 + b1) + (c1 + e1));
    }
}

// ---------------------------------------------------------------------------
// Kernel 4: column partial sums of H3 (16384 x 64) -> 128 partials per column
// ---------------------------------------------------------------------------
__global__ void colsum(const float* __restrict__ H, float* __restrict__ part) {
    __shared__ float sh[4][64];
    const int col = threadIdx.x;   // 64
    const int ty  = threadIdx.y;   // 4
    const int row0 = blockIdx.x * 128;
    float s = 0.f;
    for (int r = ty; r < 128; r += 4)
        s += H[(size_t)(row0 + r) * 64 + col];
    sh[ty][col] = s;
    __syncthreads();
    if (ty == 0)
        part[blockIdx.x * 64 + col] = sh[0][col] + sh[1][col] + sh[2][col] + sh[3][col];
}

// ---------------------------------------------------------------------------
// Kernel 5: finish mean, MLP head (elu), logits, softmax. Single block, 64 thr.
// ---------------------------------------------------------------------------
__global__ void head(const float* __restrict__ part,
                     const float* __restrict__ Wh1, const float* __restrict__ bh1,
                     const float* __restrict__ Wh2, const float* __restrict__ bh2,
                     float* __restrict__ out) {
    __shared__ float g[64], h1[32], lg[2];
    const int t = threadIdx.x;  // 64 threads
    float s = 0.f;
    for (int b = 0; b < 128; b++) s += part[b * 64 + t];
    g[t] = s * (1.0f / (float)NN);
    __syncthreads();
    if (t < MLP_H) {
        float a = bh1[t];
        #pragma unroll
        for (int k = 0; k < 64; k++) a += g[k] * Wh1[k * MLP_H + t];
        h1[t] = (a > 0.f) ? a : expm1f(a);   // elu, alpha=1
    }
    __syncthreads();
    if (t < NCLS) {
        float a = bh2[t];
        #pragma unroll
        for (int k = 0; k < MLP_H; k++) a += h1[k] * Wh2[k * NCLS + t];
        lg[t] = a;
        out[t] = a;                          // logits
    }
    __syncthreads();
    if (t == 0) {
        const float mx = fmaxf(lg[0], lg[1]);
        const float e0 = expf(lg[0] - mx), e1 = expf(lg[1] - mx);
        const float inv = 1.f / (e0 + e1);
        out[2] = e0 * inv;                   // probs
        out[3] = e1 * inv;
    }
}

// ---------------------------------------------------------------------------
extern "C" void kernel_launch(void* const* d_in, const int* in_sizes, int n_in,
                              void* d_out, int out_size) {
    const float* nf   = (const float*)d_in[0];   // [N, 64]
    const float* adj  = (const float*)d_in[1];   // [N, N]
    const float* W0   = (const float*)d_in[2];   // [64, 32]
    const float* b0   = (const float*)d_in[3];
    const float* W1   = (const float*)d_in[4];   // [32, 48]
    const float* b1   = (const float*)d_in[5];
    const float* W2   = (const float*)d_in[6];   // [48, 64]
    const float* b2   = (const float*)d_in[7];
    const float* Wh1  = (const float*)d_in[8];   // [64, 32]
    const float* bh1  = (const float*)d_in[9];
    const float* Wh2  = (const float*)d_in[10];  // [32, 2]
    const float* bh2  = (const float*)d_in[11];
    float* out = (float*)d_out;

    float *bufA, *bufB, *pt, *dinv;
    cudaGetSymbolAddress((void**)&bufA, d_bufA);
    cudaGetSymbolAddress((void**)&bufB, d_bufB);
    cudaGetSymbolAddress((void**)&pt,   d_part);
    cudaGetSymbolAddress((void**)&dinv, d_dinv);

    // gemm1 computes RAW nf@W0 (MODE 3: no dinv dependency) -> legal before
    // build_sparse; single launch (the 3-way split cost ~5us last round).
    gemm_scale<IN_DIM, L0, 256, 3><<<NN / 32, 256>>>(nf, W0, nullptr, nullptr, bufA);

    // 1 GiB streaming pass; HBM-bound, double-buffered prefetch
    build_sparse<<<NN / 8, 256>>>(adj);

    // layer 1 aggregate: dinv applied per-neighbor inside (MODE 0)
    spmm_agg<L0, 0><<<NN / 8, 256>>>(bufA, b0, bufB);     // bufB = S1 = dinv.h1

    // layer 2 (aggregate-first: gather width 32, then 32->48 GEMM)
    spmm_agg<L0, 1><<<NN / 8, 256>>>(bufB, nullptr, bufA);                  // z2
    gemm_scale<L0, L1, 384, 1><<<NN / 32, 384>>>(bufA, W1, dinv, b1, bufB); // S2

    // layer 3 (aggregate-first: gather width 48, then 48->64 GEMM)
    spmm_agg<L1, 1><<<NN / 8, 256>>>(bufB, nullptr, bufA);                  // z3
    gemm_scale<L1, L2, 512, 2><<<NN / 32, 512>>>(bufA, W2, dinv, b2, bufB); // h3

    // mean-pool + MLP + softmax
    colsum<<<128, dim3(64, 4)>>>(bufB, pt);
    head<<<1, 64>>>(pt, Wh1, bh1, Wh2, bh2, out);
}